// round 14
// baseline (speedup 1.0000x reference)
#include <cuda_runtime.h>
#include <math.h>

// x, x_r : (1, 3, 32, 512, 512) float32
// size=64 -> hc=wc=32 ; 16x16 patches per frame ; t=32
// patch mean = sum(|x - x_r|)/(2*3072) ; out = log(mean_t(max_patches))
// Deferred scaling: out = log( sum_t(max_p sum|dx|) / (32*6144) )
//
// DATAPATH A/B: replace LDG->RF with cp.async (LDGSTS) GMEM->SMEM. LDGSTS
// bypasses the register file and LDG writeback; depth is not RF-limited
// (B300: rt=8cyc/op, no depth cap). If the 5.8TB/s plateau was a per-warp
// LDG/scoreboard limit this lifts it; if it's the LTS fabric cap, no change.
// Same 8192x256 patch-per-CTA shape and identical deterministic reduction.

#define T_DIM 32
#define NPATCH 8192
#define HW 512
#define TSTRIDE (512u * 512u)
#define CSTRIDE (32u * 512u * 512u)

__device__ int          g_frame_max[T_DIM];   // float bits; >=0 so int order == float order
__device__ unsigned int g_done_count;

__global__ __launch_bounds__(256, 8)
void patch_loss_kernel(const float* __restrict__ x, const float* __restrict__ xr,
                       float* __restrict__ out) {
    const int p  = blockIdx.x;          // t*256 + ph*16 + pw
    const int t  = p >> 8;
    const int ph = (p >> 4) & 15;
    const int pw = p & 15;

    // 24KB tile: 768 float4 of x then 768 float4 of x_r
    __shared__ float4 tile[1536];

    // thread slot: row = tid/8 (0..31), col4 = (tid%8)*4 ; same for all channels
    const int row = threadIdx.x >> 3;
    const int col = (threadIdx.x & 7) << 2;
    const size_t base = (size_t)t * TSTRIDE
                      + (size_t)(ph * 32 + row) * HW
                      + (size_t)(pw * 32 + col);
    const float* px = x  + base;
    const float* pr = xr + base;

    // ---- 6 x 16B cp.async per thread: GMEM -> SMEM, no RF involvement ----
    {
        unsigned sx = (unsigned)__cvta_generic_to_shared(&tile[threadIdx.x]);
        unsigned sr = (unsigned)__cvta_generic_to_shared(&tile[768 + threadIdx.x]);
        #pragma unroll
        for (int c = 0; c < 3; ++c) {
            asm volatile("cp.async.cg.shared.global [%0], [%1], 16;"
                         :: "r"(sx + c * 256 * 16), "l"(px + (size_t)c * CSTRIDE) : "memory");
            asm volatile("cp.async.cg.shared.global [%0], [%1], 16;"
                         :: "r"(sr + c * 256 * 16), "l"(pr + (size_t)c * CSTRIDE) : "memory");
        }
        asm volatile("cp.async.commit_group;" ::: "memory");
        asm volatile("cp.async.wait_group 0;" ::: "memory");
    }
    __syncthreads();

    // consume from SMEM (conflict-free: consecutive 16B per lane)
    float acc = 0.0f;
    #pragma unroll
    for (int c = 0; c < 3; ++c) {
        const float4 a = tile[c * 256 + threadIdx.x];
        const float4 b = tile[768 + c * 256 + threadIdx.x];
        acc += fabsf(a.x - b.x) + fabsf(a.y - b.y)
             + fabsf(a.z - b.z) + fabsf(a.w - b.w);
    }

    // intra-warp reduce
    #pragma unroll
    for (int o = 16; o > 0; o >>= 1)
        acc += __shfl_xor_sync(0xFFFFFFFFu, acc, o);

    __shared__ float s[8];
    if ((threadIdx.x & 31) == 0) s[threadIdx.x >> 5] = acc;
    __syncthreads();

    if (threadIdx.x < 32) {
        const int lane = threadIdx.x;
        float v = (lane < 8) ? s[lane] : 0.0f;
        #pragma unroll
        for (int o = 16; o > 0; o >>= 1)
            v += __shfl_xor_sync(0xFFFFFFFFu, v, o);   // lane-uniform block total

        unsigned int prev = 0;
        if (lane == 0) {
            // REDG max (no return), L2-side
            asm volatile("red.global.max.s32 [%0], %1;"
                         :: "l"(&g_frame_max[t]), "r"(__float_as_int(v)) : "memory");
            // release-ordered ticket: orders the red above, no L1-flushing fence
            asm volatile("atom.release.gpu.global.add.u32 %0, [%1], 1;"
                         : "=r"(prev) : "l"(&g_done_count) : "memory");
        }
        prev = __shfl_sync(0xFFFFFFFFu, prev, 0);

        if (prev == NPATCH - 1) {                       // last CTA: finalize
            asm volatile("fence.acq_rel.gpu;" ::: "memory");
            float sum = __int_as_float(__ldcg(&g_frame_max[lane]));
            #pragma unroll
            for (int o = 16; o > 0; o >>= 1)
                sum += __shfl_xor_sync(0xFFFFFFFFu, sum, o);
            if (lane == 0) {
                *out = logf(sum / (32.0f * 6144.0f));
                g_done_count = 0u;                      // re-arm for next replay
            }
            __syncwarp();
            g_frame_max[lane] = 0;                      // re-arm (after reads)
        }
    }
}

extern "C" void kernel_launch(void* const* d_in, const int* in_sizes, int n_in,
                              void* d_out, int out_size) {
    const float* x  = (const float*)d_in[0];
    const float* xr = (const float*)d_in[1];
    patch_loss_kernel<<<NPATCH, 256>>>(x, xr, (float*)d_out);
}

// round 15
// speedup vs baseline: 1.0072x; 1.0072x over previous
#include <cuda_runtime.h>
#include <math.h>

// x, x_r : (1, 3, 32, 512, 512) float32
// size=64 -> hc=wc=32 ; 16x16 patches per frame ; t=32
// patch mean = sum(|x-x_r|)/(2*3072) ; out = log(mean_t(max_patches))
// Deferred scaling: out = log( sum_t(max_p sum|dx|) / (32*6144) )
//
// SLAB kernel: CTA = (t, ph) = 32 full 512-wide rows x 3 channels. All 16
// patches of the patch-row are reduced INSIDE the CTA -> contiguous 64KB
// streams with NO cross-CTA joins and NO mid-kernel fences (R10's regression
// is confounded by its 512 L1-flushing fences; this isolates contiguity).
// 512 CTAs x 512 threads, occ 4 -> all CTAs resident.

#define T_DIM 32
#define NCTA 512             // 32 t * 16 ph
#define HW 512
#define TSTRIDE (512u * 512u)
#define CSTRIDE (32u * 512u * 512u)

__device__ int          g_frame_max[T_DIM];   // float bits; >=0 so int order == float order
__device__ unsigned int g_done_count;

__device__ __forceinline__ float4 ldcs4(const float* p) {
    float4 v;
    asm volatile("ld.global.cs.v4.f32 {%0,%1,%2,%3}, [%4];"
                 : "=f"(v.x), "=f"(v.y), "=f"(v.z), "=f"(v.w) : "l"(p));
    return v;
}

__global__ __launch_bounds__(512, 4)
void patch_loss_kernel(const float* __restrict__ x, const float* __restrict__ xr,
                       float* __restrict__ out) {
    const int bid = blockIdx.x;
    const int t   = bid >> 4;
    const int ph  = bid & 15;
    const int tid = threadIdx.x;

    // 512 threads x float4 = 2048 floats = 4 rows per step; 8 steps = 32 rows.
    // Thread's column is fixed: col = (tid*4) % 512  ->  pw = col/32 fixed.
    const int rowoff = tid >> 7;              // 0..3 row within each 4-row step
    const int colf   = (tid & 127) << 2;      // float column 0..508
    const size_t base = (size_t)t * TSTRIDE
                      + (size_t)(ph * 32 + rowoff) * HW
                      + (size_t)colf;
    const float* px = x  + base;
    const float* pr = xr + base;

    float acc = 0.0f;
    #pragma unroll
    for (int c = 0; c < 3; ++c) {
        #pragma unroll
        for (int i = 0; i < 8; ++i) {         // serial pairs (measured-best MLP)
            const size_t off = (size_t)c * CSTRIDE + (size_t)i * (4u * HW);
            const float4 a = ldcs4(px + off);
            const float4 b = ldcs4(pr + off);
            acc += fabsf(a.x - b.x) + fabsf(a.y - b.y)
                 + fabsf(a.z - b.z) + fabsf(a.w - b.w);
        }
    }

    // 8-lane segmented reduce: lanes l..l+7 of a warp share one pw
    acc += __shfl_xor_sync(0xFFFFFFFFu, acc, 4);
    acc += __shfl_xor_sync(0xFFFFFFFFu, acc, 2);
    acc += __shfl_xor_sync(0xFFFFFFFFu, acc, 1);

    // warp w (0..15) covers pw = (w%4)*4 + lane/8 ; slot = w/4 (row group)
    __shared__ float s[16][4];
    const int wid = tid >> 5, lane = tid & 31;
    if ((lane & 7) == 0) {
        const int pw = ((wid & 3) << 2) + (lane >> 3);
        s[pw][wid >> 2] = acc;
    }
    __syncthreads();

    if (tid < 32) {
        unsigned int prev = 0;
        if (tid < 16) {                       // thread i owns patch (t, ph, pw=i)
            const float total = s[tid][0] + s[tid][1] + s[tid][2] + s[tid][3];
            asm volatile("red.global.max.s32 [%0], %1;"
                         :: "l"(&g_frame_max[t]), "r"(__float_as_int(total)) : "memory");
        }
        __syncwarp();
        if (tid == 0) {
            asm volatile("atom.release.gpu.global.add.u32 %0, [%1], 1;"
                         : "=r"(prev) : "l"(&g_done_count) : "memory");
        }
        prev = __shfl_sync(0xFFFFFFFFu, prev, 0);

        if (prev == NCTA - 1) {               // last CTA: finalize
            asm volatile("fence.acq_rel.gpu;" ::: "memory");
            float sum = __int_as_float(__ldcg(&g_frame_max[tid]));
            #pragma unroll
            for (int o = 16; o > 0; o >>= 1)
                sum += __shfl_xor_sync(0xFFFFFFFFu, sum, o);
            if (tid == 0) {
                *out = logf(sum / (32.0f * 6144.0f));
                g_done_count = 0u;            // re-arm for next replay
            }
            __syncwarp();
            g_frame_max[tid] = 0;             // re-arm (after reads)
        }
    }
}

extern "C" void kernel_launch(void* const* d_in, const int* in_sizes, int n_in,
                              void* d_out, int out_size) {
    const float* x  = (const float*)d_in[0];
    const float* xr = (const float*)d_in[1];
    patch_loss_kernel<<<NCTA, 512>>>(x, xr, (float*)d_out);
}